// round 7
// baseline (speedup 1.0000x reference)
#include <cuda_runtime.h>
#include <cuda_bf16.h>
#include <math.h>

// ---------------- problem constants ----------------
#define VOCAB 50257
#define EMBD  32
#define HID   8
#define NB    48     // batch
#define NT    128    // seq
#define NROWS (NB*NT)          // 6144
#define VP    51200            // padded vocab width (400 chunks of 128)
#define NCH   400              // chunks of 128 cols
#define VS    16               // vocab splits
#define CPC   (NCH/VS)         // 25 chunks per CTA

// ---------------- device scratch (no cudaMalloc allowed) ----------------
__device__ __align__(16) float g_W4[4 * 16 * VP];   // 4 shifted copies of h2o, padded
__device__ __align__(16) float g_Bs[NB * VP];       // per-b shifted bias, padded with -1e30
__device__ __align__(16) float g_E [NB * NT * HID]; // E[b][t][j] = emb @ i2h[:32]
__device__ __align__(16) float g_H [NB * NT * 16];  // H[b][t][0:8]=hf_used, [8:16]=hb_used
__device__ float g_Zpart[NROWS * VS];
__device__ float g_LZ  [NROWS];

typedef unsigned long long u64;

// ---------------- f32x2 helpers (sm_103a packed fp32) ----------------
__device__ __forceinline__ u64 pk2(float x) {
    u64 r; asm("mov.b64 %0,{%1,%1};" : "=l"(r) : "f"(x)); return r;
}
__device__ __forceinline__ u64 f2fma(u64 a, u64 b, u64 c) {
    u64 d; asm("fma.rn.f32x2 %0,%1,%2,%3;" : "=l"(d) : "l"(a), "l"(b), "l"(c)); return d;
}
__device__ __forceinline__ u64 f2add(u64 a, u64 b) {
    u64 d; asm("add.rn.f32x2 %0,%1,%2;" : "=l"(d) : "l"(a), "l"(b)); return d;
}
__device__ __forceinline__ float2 up2(u64 a) {
    float2 f; asm("mov.b64 {%0,%1},%2;" : "=f"(f.x), "=f"(f.y) : "l"(a)); return f;
}

// ---------------- fused prep: shifted/padded W copies + shifted bias ----------------
#define W_TOTAL (4 * 16 * VP)
#define B_TOTAL (NB * VP)
__global__ void prep_kernel(const float* __restrict__ h2o,
                            const float* __restrict__ bias) {
    int idx = blockIdx.x * blockDim.x + threadIdx.x;
    if (idx < W_TOTAL) {
        int s = idx / (16 * VP);
        int rem = idx - s * (16 * VP);
        int k = rem / VP;
        int i = rem - k * VP;
        int lo = i - s;
        float v = 0.0f;
        if (lo >= 0 && lo < VOCAB) v = h2o[k * VOCAB + lo];
        g_W4[idx] = v;
    } else {
        int j = idx - W_TOTAL;
        if (j >= B_TOTAL) return;
        int b = j / VP;
        int i = j - b * VP;
        int s = b & 3;
        int lo = i - s;
        float v = -1e30f;
        if (lo >= 0 && lo < VOCAB) v = bias[b * VOCAB + lo];
        g_Bs[j] = v;
    }
}

// ---------------- E = gather(we, ids) @ i2h[0:32,:] ----------------
__global__ void emb_kernel(const int* __restrict__ ids,
                           const float* __restrict__ we,
                           const float* __restrict__ i2h) {
    int gid = blockIdx.x * blockDim.x + threadIdx.x;  // 6144*8 threads
    if (gid >= NROWS * HID) return;
    int r = gid >> 3;          // row in (t,b) order
    int j = gid & 7;
    int t = r / NB;
    int b = r - t * NB;
    int id = ids[r];
    const float* wr = we + (long)id * EMBD;
    float acc = 0.0f;
#pragma unroll
    for (int k = 0; k < EMBD; k++)
        acc += __ldg(wr + k) * __ldg(i2h + k * HID + j);
    g_E[((b << 7) + t) * HID + j] = acc;
}

// ---------------- RNN scans: 96 warps (48 b x 2 dir), E prefetched ----------------
__global__ void rnn_kernel(const float* __restrict__ i2h,
                           const float* __restrict__ h0f,
                           const float* __restrict__ h0b) {
    int wg = blockIdx.x * (blockDim.x >> 5) + (threadIdx.x >> 5);  // 0..95
    if (wg >= 2 * NB) return;
    int lane = threadIdx.x & 31;
    int j = lane & 7;
    int dir = (wg >= NB) ? 1 : 0;
    int b = wg - dir * NB;

    float U[HID];
#pragma unroll
    for (int kk = 0; kk < HID; kk++)
        U[kk] = i2h[(EMBD + kk) * HID + j];

    float h = dir ? h0b[b * HID + j] : h0f[b * HID + j];

    int t_first = dir ? (NT - 1) : 0;
    float e_cur = g_E[((b << 7) + t_first) * HID + j];

    for (int step = 0; step < NT; step++) {
        int t = dir ? (NT - 1 - step) : step;
        float e_next = 0.0f;
        if (step + 1 < NT) {
            int tn = dir ? (NT - 2 - step) : (step + 1);
            e_next = g_E[((b << 7) + tn) * HID + j];
        }
        if (lane < HID)
            g_H[((b << 7) + t) * 16 + dir * HID + j] = h;  // state BEFORE consuming emb[t]
        float acc = e_cur;
#pragma unroll
        for (int kk = 0; kk < HID; kk++)
            acc += __shfl_sync(0xFFFFFFFFu, h, kk) * U[kk];
        h = tanhf(acc);
        e_cur = e_next;
    }
}

// ---------------- main passes ----------------
// grid: 48 b * 16 vocab splits = 768 CTAs, 256 threads, occ 2.
// CTA = (b, vocab split), covers ALL 128 t-rows. Warp owns 16 rows; lane owns
// 4 cols/chunk. wf/FFMA2 = 2/16 + 1/4 = 0.375 -> fma-bound, ~105 regs (no spill).
template<int PASS>
__global__ __launch_bounds__(256, 2) void pass_kernel(float* __restrict__ out) {
    int bx = blockIdx.x;
    int vs = bx & (VS - 1);
    int b = bx >> 4;
    int s = b & 3;

    const float* __restrict__ W  = g_W4 + s * (16 * VP);
    const float* __restrict__ Bp = g_Bs + b * VP;

    __shared__ __align__(16) u64 smh[128 * 16];  // (h,h) packed per row,k  (16 KB)
    __shared__ u64 smlz[128];                    // (-lz,-lz) packed

    int tid = threadIdx.x;
    for (int i = tid; i < 2048; i += 256) {
        float v = g_H[(b << 7) * 16 + i];
        smh[i] = pk2(v);
    }
    if (PASS == 2 && tid < 128) {
        float lz = g_LZ[(b << 7) + tid];
        smlz[tid] = pk2(-lz);
    }
    __syncthreads();

    int warp = tid >> 5, lane = tid & 31;
    int r0 = warp << 4;                          // 16 rows per warp
    float zz[16];
#pragma unroll
    for (int r = 0; r < 16; r++) zz[r] = 0.0f;

    for (int ci = 0; ci < CPC; ci++) {
        int col = ((ci << 4) + vs) * 128 + (lane << 2);
        u64 wA[16], wB[16];
#pragma unroll
        for (int k = 0; k < 16; k++) {
            ulonglong2 wk = *(const ulonglong2*)(W + k * VP + col);
            wA[k] = wk.x; wB[k] = wk.y;
        }
        ulonglong2 bb = *(const ulonglong2*)(Bp + col);

#pragma unroll
        for (int r = 0; r < 16; r++) {
            int row = r0 + r;
            u64 a0 = bb.x, a1 = bb.y;
            const ulonglong2* hp2 = (const ulonglong2*)&smh[row << 4];
#pragma unroll
            for (int k2 = 0; k2 < 8; k2++) {
                ulonglong2 hh = hp2[k2];
                a0 = f2fma(hh.x, wA[2 * k2],     a0);
                a1 = f2fma(hh.x, wB[2 * k2],     a1);
                a0 = f2fma(hh.y, wA[2 * k2 + 1], a0);
                a1 = f2fma(hh.y, wB[2 * k2 + 1], a1);
            }
            if (PASS == 1) {
                float2 p = up2(a0), q = up2(a1);
                zz[r] += (__expf(p.x) + __expf(p.y)) + (__expf(q.x) + __expf(q.y));
            } else {
                a0 = f2add(a0, smlz[row]);
                a1 = f2add(a1, smlz[row]);
                long rowbase = (long)(row * NB + b) * VOCAB;
                int lo = col - s;
                float2 p = up2(a0), q = up2(a1);
                if (lo >= 0 && lo + 4 <= VOCAB) {
                    // rowbase % 4 == b % 4 == s, lo % 4 == (4 - s) % 4 -> 16B aligned
                    float4 v4 = make_float4(p.x, p.y, q.x, q.y);
                    __stcs((float4*)(out + rowbase + lo), v4);
                } else {
                    float vals[4] = {p.x, p.y, q.x, q.y};
#pragma unroll
                    for (int e = 0; e < 4; e++) {
                        int v = lo + e;
                        if (v >= 0 && v < VOCAB) __stcs(out + rowbase + v, vals[e]);
                    }
                }
            }
        }
    }

    if (PASS == 1) {
#pragma unroll
        for (int r = 0; r < 16; r++) {
            float zr = zz[r];
#pragma unroll
            for (int o = 16; o; o >>= 1) zr += __shfl_xor_sync(0xFFFFFFFFu, zr, o);
            if (lane == 0)
                g_Zpart[((b << 7) + r0 + r) * VS + vs] = zr;
        }
    }
}

// ---------------- reduce Z partials -> logZ ----------------
__global__ void reduce_kernel() {
    int r = blockIdx.x * blockDim.x + threadIdx.x;
    if (r >= NROWS) return;
    float ssum = 0.0f;
#pragma unroll
    for (int v = 0; v < VS; v++) ssum += g_Zpart[r * VS + v];
    g_LZ[r] = logf(ssum);
}

// ---------------- launch ----------------
extern "C" void kernel_launch(void* const* d_in, const int* in_sizes, int n_in,
                              void* d_out, int out_size) {
    const int*   ids  = (const int*)  d_in[0];
    const float* we   = (const float*)d_in[1];
    const float* i2h  = (const float*)d_in[2];
    const float* h2o  = (const float*)d_in[3];
    const float* bias = (const float*)d_in[4];
    const float* h0f  = (const float*)d_in[5];
    const float* h0b  = (const float*)d_in[6];
    float* out = (float*)d_out;

    {
        int n = W_TOTAL + B_TOTAL;
        prep_kernel<<<(n + 255) / 256, 256>>>(h2o, bias);       // launch 0
    }
    {
        int n = NROWS * HID;
        emb_kernel<<<(n + 255) / 256, 256>>>(ids, we, i2h);     // launch 1
    }
    rnn_kernel<<<24, 128>>>(i2h, h0f, h0b);                     // launch 2

    pass_kernel<1><<<NB * VS, 256>>>(out);                      // launch 3 (ncu capture slot)
    reduce_kernel<<<(NROWS + 255) / 256, 256>>>();              // launch 4
    pass_kernel<2><<<NB * VS, 256>>>(out);                      // launch 5
}

// round 8
// speedup vs baseline: 3.0264x; 3.0264x over previous
#include <cuda_runtime.h>
#include <cuda_bf16.h>
#include <math.h>

// ---------------- problem constants ----------------
#define VOCAB 50257
#define EMBD  32
#define HID   8
#define NB    48     // batch
#define NT    128    // seq
#define NROWS (NB*NT)          // 6144
#define VP    51200            // padded vocab width (400 chunks of 128)
#define NCH   400              // chunks of 128 cols
#define VS    16               // vocab splits
#define CPC   (NCH/VS)         // 25 chunks per CTA

// ---------------- device scratch (no cudaMalloc allowed) ----------------
__device__ __align__(16) float g_W4[4 * 16 * VP];   // 4 shifted copies of h2o, padded
__device__ __align__(16) float g_Bs[NB * VP];       // per-b shifted bias, padded with -1e30
__device__ __align__(16) float g_E [NB * NT * HID]; // E[b][t][j] = emb @ i2h[:32]
__device__ __align__(16) float g_H [NB * NT * 16];  // H[b][t][0:8]=hf_used, [8:16]=hb_used
__device__ float g_Zpart[NROWS * VS];
__device__ float g_LZ  [NROWS];

typedef unsigned long long u64;

// ---------------- f32x2 helpers (sm_103a packed fp32) ----------------
__device__ __forceinline__ u64 pk2(float x) {
    u64 r; asm("mov.b64 %0,{%1,%1};" : "=l"(r) : "f"(x)); return r;
}
__device__ __forceinline__ u64 f2fma(u64 a, u64 b, u64 c) {
    u64 d; asm("fma.rn.f32x2 %0,%1,%2,%3;" : "=l"(d) : "l"(a), "l"(b), "l"(c)); return d;
}
__device__ __forceinline__ u64 f2add(u64 a, u64 b) {
    u64 d; asm("add.rn.f32x2 %0,%1,%2;" : "=l"(d) : "l"(a), "l"(b)); return d;
}
__device__ __forceinline__ float2 up2(u64 a) {
    float2 f; asm("mov.b64 {%0,%1},%2;" : "=f"(f.x), "=f"(f.y) : "l"(a)); return f;
}
__device__ __forceinline__ void cp16(void* dst, const void* src) {
    unsigned saddr = (unsigned)__cvta_generic_to_shared(dst);
    asm volatile("cp.async.cg.shared.global [%0], [%1], 16;" :: "r"(saddr), "l"(src));
}

// ---------------- fused prep: shifted/padded W copies + shifted bias ----------------
#define W_TOTAL (4 * 16 * VP)
#define B_TOTAL (NB * VP)
__global__ void prep_kernel(const float* __restrict__ h2o,
                            const float* __restrict__ bias) {
    int idx = blockIdx.x * blockDim.x + threadIdx.x;
    if (idx < W_TOTAL) {
        int s = idx / (16 * VP);
        int rem = idx - s * (16 * VP);
        int k = rem / VP;
        int i = rem - k * VP;
        int lo = i - s;
        float v = 0.0f;
        if (lo >= 0 && lo < VOCAB) v = h2o[k * VOCAB + lo];
        g_W4[idx] = v;
    } else {
        int j = idx - W_TOTAL;
        if (j >= B_TOTAL) return;
        int b = j / VP;
        int i = j - b * VP;
        int s = b & 3;
        int lo = i - s;
        float v = -1e30f;
        if (lo >= 0 && lo < VOCAB) v = bias[b * VOCAB + lo];
        g_Bs[j] = v;
    }
}

// ---------------- E = gather(we, ids) @ i2h[0:32,:] ----------------
__global__ void emb_kernel(const int* __restrict__ ids,
                           const float* __restrict__ we,
                           const float* __restrict__ i2h) {
    int gid = blockIdx.x * blockDim.x + threadIdx.x;
    if (gid >= NROWS * HID) return;
    int r = gid >> 3;
    int j = gid & 7;
    int t = r / NB;
    int b = r - t * NB;
    int id = ids[r];
    const float* wr = we + (long)id * EMBD;
    float acc = 0.0f;
#pragma unroll
    for (int k = 0; k < EMBD; k++)
        acc += __ldg(wr + k) * __ldg(i2h + k * HID + j);
    g_E[((b << 7) + t) * HID + j] = acc;
}

// ---------------- RNN scans: 96 warps (48 b x 2 dir), fast tanh ----------------
__global__ void rnn_kernel(const float* __restrict__ i2h,
                           const float* __restrict__ h0f,
                           const float* __restrict__ h0b) {
    int wg = blockIdx.x * (blockDim.x >> 5) + (threadIdx.x >> 5);
    if (wg >= 2 * NB) return;
    int lane = threadIdx.x & 31;
    int j = lane & 7;
    int dir = (wg >= NB) ? 1 : 0;
    int b = wg - dir * NB;

    float U[HID];
#pragma unroll
    for (int kk = 0; kk < HID; kk++)
        U[kk] = i2h[(EMBD + kk) * HID + j];

    float h = dir ? h0b[b * HID + j] : h0f[b * HID + j];

    int t_first = dir ? (NT - 1) : 0;
    float e_cur = g_E[((b << 7) + t_first) * HID + j];

    for (int step = 0; step < NT; step++) {
        int t = dir ? (NT - 1 - step) : step;
        float e_next = 0.0f;
        if (step + 1 < NT) {
            int tn = dir ? (NT - 2 - step) : (step + 1);
            e_next = g_E[((b << 7) + tn) * HID + j];
        }
        if (lane < HID)
            g_H[((b << 7) + t) * 16 + dir * HID + j] = h;
        float acc = e_cur;
#pragma unroll
        for (int kk = 0; kk < HID; kk++)
            acc += __shfl_sync(0xFFFFFFFFu, h, kk) * U[kk];
        // fast tanh: (e^{2x}-1)/(e^{2x}+1) via MUFU (err ~1e-6, tolerance 1e-3)
        float ex = __expf(2.0f * acc);
        h = (ex - 1.0f) * __fdividef(1.0f, ex + 1.0f);
        e_cur = e_next;
    }
}

// ---------------- main passes ----------------
// grid: 48 b * 2 t-tiles * 16 vs = 1536 CTAs, 256 threads, occ 2.
// W streamed gmem -> smem (triple-buffered cp.async, 2 chunks ahead), K in
// groups of 4 (W regs <= 8 u64). Warp owns 8 rows; lane owns 4 cols/chunk.
// acc 16 u64 + W 8 u64 + misc ~= 85 regs -> no spill under 128 cap.
template<int PASS>
__global__ __launch_bounds__(256, 2) void pass_kernel(float* __restrict__ out) {
    int bx = blockIdx.x;
    int vs = bx & (VS - 1);
    int tmp = bx >> 4;
    int tt = tmp & 1;
    int b = tmp >> 1;
    int t0 = tt << 6;
    int s = b & 3;

    const float* __restrict__ W  = g_W4 + s * (16 * VP);
    const float* __restrict__ Bp = g_Bs + b * VP;

    __shared__ __align__(16) float smw[3][16 * 128];  // 3 x 8KB W chunk buffers
    __shared__ __align__(16) u64 smh[64 * 16];        // (h,h) packed per row,k
    __shared__ u64 smlz[64];                          // (-lz,-lz) packed

    int tid = threadIdx.x;

    // prefetch of one W chunk: 512 float4; each thread copies 2
    auto prefetch = [&](int ci, int buf) {
        int colbase = ((ci << 4) + vs) * 128;
        const float* src = W + colbase;
#pragma unroll
        for (int h = 0; h < 2; h++) {
            int f4 = tid + h * 256;          // 0..511
            int k = f4 >> 5;                 // 32 float4 per k-row
            int c = (f4 & 31) << 2;
            cp16(&smw[buf][k * 128 + c], src + (long)k * VP + c);
        }
        asm volatile("cp.async.commit_group;" ::: "memory");
    };

    prefetch(0, 0);
    prefetch(1, 1);

    for (int i = tid; i < 1024; i += 256)
        smh[i] = pk2(g_H[(((b << 7) + t0) << 4) + i]);
    if (PASS == 2 && tid < 64)
        smlz[tid] = pk2(-g_LZ[(b << 7) + t0 + tid]);

    int warp = tid >> 5, lane = tid & 31;
    int r0 = warp << 3;                               // 8 rows per warp
    float zz[8];
#pragma unroll
    for (int r = 0; r < 8; r++) zz[r] = 0.0f;

    for (int ci = 0; ci < CPC; ci++) {
        int p = ci % 3;
        if (ci < CPC - 1) asm volatile("cp.async.wait_group 1;" ::: "memory");
        else              asm volatile("cp.async.wait_group 0;" ::: "memory");
        __syncthreads();   // everyone's cp.async for chunk ci landed (also covers smh on ci==0)

        int col = ((ci << 4) + vs) * 128 + (lane << 2);
        ulonglong2 bb = *(const ulonglong2*)(Bp + col);
        u64 a[8][2];
#pragma unroll
        for (int r = 0; r < 8; r++) { a[r][0] = bb.x; a[r][1] = bb.y; }

        const float* wp0 = &smw[p][lane << 2];
#pragma unroll
        for (int kg = 0; kg < 4; kg++) {
            const float* wp = wp0 + (kg << 9);        // kg*4 k-rows * 128
            ulonglong2 w0 = *(const ulonglong2*)(wp);
            ulonglong2 w1 = *(const ulonglong2*)(wp + 128);
            ulonglong2 w2 = *(const ulonglong2*)(wp + 256);
            ulonglong2 w3 = *(const ulonglong2*)(wp + 384);
#pragma unroll
            for (int r = 0; r < 8; r++) {
                const ulonglong2* hp = (const ulonglong2*)&smh[((r0 + r) << 4) + (kg << 2)];
                ulonglong2 h01 = hp[0];
                ulonglong2 h23 = hp[1];
                a[r][0] = f2fma(h01.x, w0.x, a[r][0]);
                a[r][1] = f2fma(h01.x, w0.y, a[r][1]);
                a[r][0] = f2fma(h01.y, w1.x, a[r][0]);
                a[r][1] = f2fma(h01.y, w1.y, a[r][1]);
                a[r][0] = f2fma(h23.x, w2.x, a[r][0]);
                a[r][1] = f2fma(h23.x, w2.y, a[r][1]);
                a[r][0] = f2fma(h23.y, w3.x, a[r][0]);
                a[r][1] = f2fma(h23.y, w3.y, a[r][1]);
            }
        }

#pragma unroll
        for (int r = 0; r < 8; r++) {
            if (PASS == 1) {
                float2 pp = up2(a[r][0]), qq = up2(a[r][1]);
                zz[r] += (__expf(pp.x) + __expf(pp.y)) + (__expf(qq.x) + __expf(qq.y));
            } else {
                int row = r0 + r;
                u64 a0 = f2add(a[r][0], smlz[row]);
                u64 a1 = f2add(a[r][1], smlz[row]);
                long rowbase = (long)((t0 + row) * NB + b) * VOCAB;
                int lo = col - s;
                float2 pp = up2(a0), qq = up2(a1);
                if (lo >= 0 && lo + 4 <= VOCAB) {
                    float4 v4 = make_float4(pp.x, pp.y, qq.x, qq.y);
                    __stcs((float4*)(out + rowbase + lo), v4);
                } else {
                    float vals[4] = {pp.x, pp.y, qq.x, qq.y};
#pragma unroll
                    for (int e = 0; e < 4; e++) {
                        int v = lo + e;
                        if (v >= 0 && v < VOCAB) __stcs(out + rowbase + v, vals[e]);
                    }
                }
            }
        }

        // prefetch chunk ci+2 into buf (ci+2)%3 (its last reader was iter ci-1,
        // already past this iteration's __syncthreads)
        if (ci + 2 < CPC) prefetch(ci + 2, (ci + 2) % 3);
    }

    if (PASS == 1) {
#pragma unroll
        for (int r = 0; r < 8; r++) {
            float zr = zz[r];
#pragma unroll
            for (int o = 16; o; o >>= 1) zr += __shfl_xor_sync(0xFFFFFFFFu, zr, o);
            if (lane == 0)
                g_Zpart[((b << 7) + t0 + r0 + r) * VS + vs] = zr;
        }
    }
}

// ---------------- reduce Z partials -> logZ ----------------
__global__ void reduce_kernel() {
    int r = blockIdx.x * blockDim.x + threadIdx.x;
    if (r >= NROWS) return;
    float ssum = 0.0f;
#pragma unroll
    for (int v = 0; v < VS; v++) ssum += g_Zpart[r * VS + v];
    g_LZ[r] = logf(ssum);
}

// ---------------- launch ----------------
extern "C" void kernel_launch(void* const* d_in, const int* in_sizes, int n_in,
                              void* d_out, int out_size) {
    const int*   ids  = (const int*)  d_in[0];
    const float* we   = (const float*)d_in[1];
    const float* i2h  = (const float*)d_in[2];
    const float* h2o  = (const float*)d_in[3];
    const float* bias = (const float*)d_in[4];
    const float* h0f  = (const float*)d_in[5];
    const float* h0b  = (const float*)d_in[6];
    float* out = (float*)d_out;

    {
        int n = W_TOTAL + B_TOTAL;
        prep_kernel<<<(n + 255) / 256, 256>>>(h2o, bias);       // launch 0
    }
    {
        int n = NROWS * HID;
        emb_kernel<<<(n + 255) / 256, 256>>>(ids, we, i2h);     // launch 1
    }
    rnn_kernel<<<24, 128>>>(i2h, h0f, h0b);                     // launch 2

    pass_kernel<1><<<NB * 2 * VS, 256>>>(out);                  // launch 3 (ncu capture slot)
    reduce_kernel<<<(NROWS + 255) / 256, 256>>>();              // launch 4
    pass_kernel<2><<<NB * 2 * VS, 256>>>(out);                  // launch 5
}